// round 2
// baseline (speedup 1.0000x reference)
#include <cuda_runtime.h>
#include <cstdint>

#define T_ 4096
#define E_ 8
#define H_ 2048
#define I_ 4096
#define KMAX 2
#define ROWCAP (T_ * KMAX)

// ---------------- scratch (device globals: allocation-free) ----------------
__device__ int   g_k;
__device__ int   g_counts[E_];
__device__ int   g_actoff[E_];
__device__ int   g_tok[E_ * T_];
__device__ float g_w[E_ * T_];
__device__ int   g_slot_row[T_ * KMAX];         // packed row index for (token, slot)
__device__ float g_act[(size_t)ROWCAP * I_];    // SiLU(x@W1)*(x@W3), packed per expert
__device__ float g_out2[(size_t)ROWCAP * H_];   // weighted per-(token,slot) outputs

__device__ __forceinline__ float silu_f(float x) {
    return x / (1.0f + __expf(-x));
}

// ---------------- init: zero counts, read top_k ----------------
__global__ void init_kernel(const int* topk_ptr) {
    if (threadIdx.x == 0) {
        int k = topk_ptr ? *topk_ptr : 2;
        if (k < 1) k = 1;
        if (k > KMAX) k = KMAX;
        g_k = k;
    }
    if (threadIdx.x < E_) g_counts[threadIdx.x] = 0;
}

// ---------------- routing: top-k of softmax, renormalized ----------------
// softmax denom cancels under renorm: w_j = exp(l_j - m) / sum_topk exp(l - m)
__global__ void route_kernel(const float* __restrict__ logits) {
    int t = blockIdx.x * blockDim.x + threadIdx.x;
    if (t >= T_) return;
    int k = g_k;

    float l[E_];
    float mx = -1e30f;
#pragma unroll
    for (int e = 0; e < E_; e++) {
        l[e] = logits[t * E_ + e];
        mx = fmaxf(mx, l[e]);
    }
    bool used[E_];
#pragma unroll
    for (int e = 0; e < E_; e++) used[e] = false;

    int sel[KMAX];
    float sw[KMAX];
    float wsum = 0.0f;
    for (int j = 0; j < k; j++) {
        int best = 0;
        float bv = -1e30f;
#pragma unroll
        for (int e = 0; e < E_; e++) {
            if (!used[e] && l[e] > bv) { bv = l[e]; best = e; }
        }
        used[best] = true;
        sel[j] = best;
        float w = __expf(l[best] - mx);
        sw[j] = w;
        wsum += w;
    }
    for (int j = 0; j < k; j++) {
        int e = sel[j];
        float w = sw[j] / wsum;
        int p = atomicAdd(&g_counts[e], 1);
        g_tok[e * T_ + p] = t;
        g_w[e * T_ + p] = w;
        // store (e,p) packed; offsets resolved in scan_kernel epoch via g_actoff at combine
        g_slot_row[t * KMAX + j] = e * T_ + p;
    }
}

// ---------------- tiny exclusive scan over E=8 counts ----------------
__global__ void scan_kernel() {
    int off = 0;
    for (int e = 0; e < E_; e++) {
        g_actoff[e] = off;
        off += g_counts[e];
    }
}

// ---------------- GEMM1: act = SiLU(X@W1) * (X@W3), gathered rows ----------------
// Tile: 128 rows x 64 cols (of gate AND up), BK=16, 256 threads, 8x4 microtile x2
__global__ __launch_bounds__(256, 1)
void gemm1_kernel(const float* __restrict__ X, const float* __restrict__ W13) {
    int e = blockIdx.z;
    int cnt = g_counts[e];
    int rowBase = blockIdx.y * 128;
    if (rowBase >= cnt) return;
    int colBase = blockIdx.x * 64;

    __shared__ float As[16][128];
    __shared__ float Bg[16][64];
    __shared__ float Bu[16][64];
    __shared__ int toks[128];

    int tid = threadIdx.x;
    if (tid < 128) {
        int i = rowBase + tid;
        toks[tid] = (i < cnt) ? g_tok[e * T_ + i] : -1;
    }
    __syncthreads();

    float accG[8][4];
    float accU[8][4];
#pragma unroll
    for (int r = 0; r < 8; r++)
#pragma unroll
        for (int c = 0; c < 4; c++) { accG[r][c] = 0.0f; accU[r][c] = 0.0f; }

    const float* Wg = W13 + (size_t)e * H_ * (2 * I_) + colBase;
    int ty = tid >> 4;       // 0..15 -> rows ty*8..ty*8+7
    int tx = tid & 15;       // 0..15 -> cols tx*4..tx*4+3

    for (int k0 = 0; k0 < H_; k0 += 16) {
        // A tile: 128 rows x 16 k, gathered. 2 float4 per thread.
#pragma unroll
        for (int j = 0; j < 2; j++) {
            int idx = tid * 2 + j;          // 0..511
            int m = idx >> 2;               // 0..127
            int kq = idx & 3;               // float4 slot
            int tok = toks[m];
            float4 v = make_float4(0.f, 0.f, 0.f, 0.f);
            if (tok >= 0)
                v = *(const float4*)(X + (size_t)tok * H_ + k0 + kq * 4);
            As[kq * 4 + 0][m] = v.x;
            As[kq * 4 + 1][m] = v.y;
            As[kq * 4 + 2][m] = v.z;
            As[kq * 4 + 3][m] = v.w;
        }
        // B tiles: 16 k x 64 cols, gate + up
        {
            int kk = tid >> 4;
            int cq = tid & 15;
            const float* bp = Wg + (size_t)(k0 + kk) * (2 * I_) + cq * 4;
            *(float4*)&Bg[kk][cq * 4] = *(const float4*)bp;
            *(float4*)&Bu[kk][cq * 4] = *(const float4*)(bp + I_);
        }
        __syncthreads();

#pragma unroll
        for (int kk = 0; kk < 16; kk++) {
            float a[8], bg[4], bu[4];
#pragma unroll
            for (int r = 0; r < 8; r++) a[r] = As[kk][ty * 8 + r];
#pragma unroll
            for (int c = 0; c < 4; c++) { bg[c] = Bg[kk][tx * 4 + c]; bu[c] = Bu[kk][tx * 4 + c]; }
#pragma unroll
            for (int r = 0; r < 8; r++)
#pragma unroll
                for (int c = 0; c < 4; c++) {
                    accG[r][c] += a[r] * bg[c];
                    accU[r][c] += a[r] * bu[c];
                }
        }
        __syncthreads();
    }

    int off = g_actoff[e];
#pragma unroll
    for (int r = 0; r < 8; r++) {
        int i = rowBase + ty * 8 + r;
        if (i < cnt) {
            float4 v;
            v.x = silu_f(accG[r][0]) * accU[r][0];
            v.y = silu_f(accG[r][1]) * accU[r][1];
            v.z = silu_f(accG[r][2]) * accU[r][2];
            v.w = silu_f(accG[r][3]) * accU[r][3];
            *(float4*)(g_act + (size_t)(off + i) * I_ + colBase + tx * 4) = v;
        }
    }
}

// ---------------- GEMM2: out2 = w_row * (act @ W2_e) ----------------
__global__ __launch_bounds__(256, 1)
void gemm2_kernel(const float* __restrict__ W2) {
    int e = blockIdx.z;
    int cnt = g_counts[e];
    int rowBase = blockIdx.y * 128;
    if (rowBase >= cnt) return;
    int colBase = blockIdx.x * 64;
    int off = g_actoff[e];

    __shared__ float As[16][128];
    __shared__ float Bs[16][64];

    int tid = threadIdx.x;
    int ty = tid >> 4;
    int tx = tid & 15;

    float acc[8][4];
#pragma unroll
    for (int r = 0; r < 8; r++)
#pragma unroll
        for (int c = 0; c < 4; c++) acc[r][c] = 0.0f;

    const float* Wp = W2 + (size_t)e * I_ * H_ + colBase;
    const float* Ap = g_act + (size_t)off * I_;

    for (int k0 = 0; k0 < I_; k0 += 16) {
#pragma unroll
        for (int j = 0; j < 2; j++) {
            int idx = tid * 2 + j;
            int m = idx >> 2;
            int kq = idx & 3;
            int i = rowBase + m;
            float4 v = make_float4(0.f, 0.f, 0.f, 0.f);
            if (i < cnt)
                v = *(const float4*)(Ap + (size_t)i * I_ + k0 + kq * 4);
            As[kq * 4 + 0][m] = v.x;
            As[kq * 4 + 1][m] = v.y;
            As[kq * 4 + 2][m] = v.z;
            As[kq * 4 + 3][m] = v.w;
        }
        {
            int kk = tid >> 4;
            int cq = tid & 15;
            *(float4*)&Bs[kk][cq * 4] =
                *(const float4*)(Wp + (size_t)(k0 + kk) * H_ + cq * 4);
        }
        __syncthreads();

#pragma unroll
        for (int kk = 0; kk < 16; kk++) {
            float a[8], b[4];
#pragma unroll
            for (int r = 0; r < 8; r++) a[r] = As[kk][ty * 8 + r];
#pragma unroll
            for (int c = 0; c < 4; c++) b[c] = Bs[kk][tx * 4 + c];
#pragma unroll
            for (int r = 0; r < 8; r++)
#pragma unroll
                for (int c = 0; c < 4; c++) acc[r][c] += a[r] * b[c];
        }
        __syncthreads();
    }

#pragma unroll
    for (int r = 0; r < 8; r++) {
        int i = rowBase + ty * 8 + r;
        if (i < cnt) {
            float w = g_w[e * T_ + i];
            float4 v;
            v.x = w * acc[r][0];
            v.y = w * acc[r][1];
            v.z = w * acc[r][2];
            v.w = w * acc[r][3];
            *(float4*)(g_out2 + (size_t)(off + i) * H_ + colBase + tx * 4) = v;
        }
    }
}

// ---------------- combine: out[t] = sum over top-k slots (atomic-free) ----------------
__global__ void combine_kernel(float* __restrict__ out) {
    int t = blockIdx.x;
    __shared__ int rows[KMAX];
    int k = g_k;
    if (threadIdx.x < k) {
        int ep = g_slot_row[t * KMAX + threadIdx.x];  // e*T + p
        int e = ep / T_;
        int p = ep - e * T_;
        rows[threadIdx.x] = g_actoff[e] + p;
    }
    __syncthreads();
    // H_=2048 floats = 512 float4; 256 threads -> 2 iters
    for (int h4 = threadIdx.x; h4 < H_ / 4; h4 += blockDim.x) {
        float4 s = make_float4(0.f, 0.f, 0.f, 0.f);
        for (int j = 0; j < k; j++) {
            float4 v = *(const float4*)(g_out2 + (size_t)rows[j] * H_ + h4 * 4);
            s.x += v.x; s.y += v.y; s.z += v.z; s.w += v.w;
        }
        *(float4*)(out + (size_t)t * H_ + h4 * 4) = s;
    }
}

// ---------------- launch ----------------
extern "C" void kernel_launch(void* const* d_in, const int* in_sizes, int n_in,
                              void* d_out, int out_size) {
    const float* X   = (const float*)d_in[0];
    const float* RL  = (const float*)d_in[1];
    const float* W13 = (const float*)d_in[2];
    const float* W2  = (const float*)d_in[3];
    const int*   tk  = (n_in > 4) ? (const int*)d_in[4] : nullptr;

    init_kernel<<<1, 32>>>(tk);
    route_kernel<<<(T_ + 127) / 128, 128>>>(RL);
    scan_kernel<<<1, 1>>>();
    gemm1_kernel<<<dim3(I_ / 64, T_ / 128, E_), 256>>>(X, W13);
    gemm2_kernel<<<dim3(H_ / 64, T_ / 128, E_), 256>>>(W2);
    combine_kernel<<<T_, 256>>>((float*)d_out);
}

// round 4
// speedup vs baseline: 2.7358x; 2.7358x over previous
#include <cuda_runtime.h>
#include <cstdint>

#define T_ 4096
#define E_ 8
#define H_ 2048
#define I_ 4096
#define KMAX 2
#define ROWCAP (T_ * KMAX)

#define BM 128
#define BN 128
#define BK 32
#define SA 36               // padded row stride (floats): 144B = 9*16B, conflict-free
#define STAGE_BYTES 36864   // A(128*36*4=18432) + B(128*36*4=18432)
#define SMEM_BYTES (512 + 2 * STAGE_BYTES)

// ---------------- scratch ----------------
__device__ int   g_k;
__device__ int   g_counts[E_];
__device__ int   g_actoff[E_];
__device__ int   g_tok[E_ * T_];
__device__ float g_w[E_ * T_];
__device__ int   g_slot_row[T_ * KMAX];
__device__ float g_act[(size_t)ROWCAP * I_];
__device__ float g_out2[(size_t)ROWCAP * H_];

__device__ __forceinline__ float silu_f(float x) { return x / (1.0f + __expf(-x)); }

__device__ __forceinline__ uint32_t smem_u32(const void* p) {
    return (uint32_t)__cvta_generic_to_shared(p);
}
// convert 4 floats to tf32 (RNA) and store as one STS.128
__device__ __forceinline__ void sts4_tf32(uint32_t addr, float4 v) {
    uint32_t a, b, c, d;
    asm volatile("cvt.rna.tf32.f32 %0, %1;" : "=r"(a) : "f"(v.x));
    asm volatile("cvt.rna.tf32.f32 %0, %1;" : "=r"(b) : "f"(v.y));
    asm volatile("cvt.rna.tf32.f32 %0, %1;" : "=r"(c) : "f"(v.z));
    asm volatile("cvt.rna.tf32.f32 %0, %1;" : "=r"(d) : "f"(v.w));
    asm volatile("st.shared.v4.b32 [%0], {%1,%2,%3,%4};"
                 :: "r"(addr), "r"(a), "r"(b), "r"(c), "r"(d));
}
__device__ __forceinline__ uint32_t lds32(uint32_t addr) {
    uint32_t v;
    asm volatile("ld.shared.b32 %0, [%1];" : "=r"(v) : "r"(addr));
    return v;
}
// m16n8k8 tf32 mma, fp32 accumulate
__device__ __forceinline__ void mma_tf32(float* c, const uint32_t* a, const uint32_t* b) {
    asm volatile(
        "mma.sync.aligned.m16n8k8.row.col.f32.tf32.tf32.f32 "
        "{%0,%1,%2,%3}, {%4,%5,%6,%7}, {%8,%9}, {%0,%1,%2,%3};"
        : "+f"(c[0]), "+f"(c[1]), "+f"(c[2]), "+f"(c[3])
        : "r"(a[0]), "r"(a[1]), "r"(a[2]), "r"(a[3]), "r"(b[0]), "r"(b[1]));
}

// =================== init / route / scan ===================
__global__ void init_kernel(const int* topk_ptr) {
    if (threadIdx.x == 0) {
        int k = topk_ptr ? *topk_ptr : 2;
        if (k < 1) k = 1;
        if (k > KMAX) k = KMAX;
        g_k = k;
    }
    if (threadIdx.x < E_) g_counts[threadIdx.x] = 0;
}

__global__ void route_kernel(const float* __restrict__ logits) {
    int t = blockIdx.x * blockDim.x + threadIdx.x;
    if (t >= T_) return;
    int k = g_k;
    float l[E_];
    float mx = -1e30f;
#pragma unroll
    for (int e = 0; e < E_; e++) { l[e] = logits[t * E_ + e]; mx = fmaxf(mx, l[e]); }
    bool used[E_];
#pragma unroll
    for (int e = 0; e < E_; e++) used[e] = false;
    int sel[KMAX]; float sw[KMAX]; float wsum = 0.0f;
    for (int j = 0; j < k; j++) {
        int best = 0; float bv = -1e30f;
#pragma unroll
        for (int e = 0; e < E_; e++)
            if (!used[e] && l[e] > bv) { bv = l[e]; best = e; }
        used[best] = true; sel[j] = best;
        float w = __expf(l[best] - mx);
        sw[j] = w; wsum += w;
    }
    for (int j = 0; j < k; j++) {
        int e = sel[j];
        float w = sw[j] / wsum;
        int p = atomicAdd(&g_counts[e], 1);
        g_tok[e * T_ + p] = t;
        g_w[e * T_ + p] = w;
        g_slot_row[t * KMAX + j] = e * T_ + p;
    }
}

__global__ void scan_kernel() {
    int off = 0;
    for (int e = 0; e < E_; e++) { g_actoff[e] = off; off += g_counts[e]; }
}

// =================== GEMM1: act = SiLU(Xg@W1)*(Xg@W3) ===================
// block: M=128 gathered rows, 64 logical cols (128 phys: even=gate, odd=up), K=H
__global__ __launch_bounds__(256, 1)
void gemm1_kernel(const float* __restrict__ X, const float* __restrict__ W13) {
    int e = blockIdx.z;
    int cnt = g_counts[e];
    int rowBase = blockIdx.y * BM;
    if (rowBase >= cnt) return;
    int nbase = blockIdx.x * 64;      // logical col base

    extern __shared__ float smem[];
    int* toks = (int*)smem;
    uint32_t sb = smem_u32(smem);
    uint32_t Abase = sb + 512;
    uint32_t Bbase = Abase + 18432;

    int tid = threadIdx.x;
    int wid = tid >> 5, lane = tid & 31;
    int gid = lane >> 2, tig = lane & 3;
    int wm = (wid & 3) * 32, wn = (wid >> 2) * 64;

    if (tid < BM) {
        int i = rowBase + tid;
        toks[tid] = (i < cnt) ? g_tok[e * T_ + i] : -1;
    }
    __syncthreads();

    // per-thread loader geometry
    // A: q = tid&7 fixed, m = j*32 + (tid>>3)
    // B: s = tid&127 fixed, q = 2j + (tid>>7)
    const int aq = tid & 7;
    const int am0 = tid >> 3;
    const int bs = tid & 127;
    const int bqh = tid >> 7;
    const float* arow[4];
#pragma unroll
    for (int j = 0; j < 4; j++) {
        int tok = toks[am0 + j * 32];
        arow[j] = (tok >= 0) ? (X + (size_t)tok * H_) : nullptr;
    }
    // B column pointer: smem col s -> logical col c=s>>1, gate/up by s&1
    const float* colp = W13 + (size_t)e * H_ * (2 * I_) + nbase + (bs >> 1) + ((bs & 1) ? I_ : 0);
    uint32_t aaddr[4], baddr[4];
#pragma unroll
    for (int j = 0; j < 4; j++) {
        aaddr[j] = Abase + (am0 + j * 32) * (SA * 4) + aq * 16;
        baddr[j] = Bbase + bs * (SA * 4) + (2 * j + bqh) * 16;
    }

    float acc[2][8][4];
#pragma unroll
    for (int mt = 0; mt < 2; mt++)
#pragma unroll
        for (int nt = 0; nt < 8; nt++)
#pragma unroll
            for (int r = 0; r < 4; r++) acc[mt][nt][r] = 0.0f;

    float4 pa[4], pb[4];
    const int NITER = H_ / BK;   // 64

    // prologue: load+store stage 0
#pragma unroll
    for (int j = 0; j < 4; j++) {
        pa[j] = arow[j] ? *(const float4*)(arow[j] + aq * 4) : make_float4(0, 0, 0, 0);
        int kk = (2 * j + bqh) * 4;
        pb[j].x = colp[(size_t)(kk + 0) * (2 * I_)];
        pb[j].y = colp[(size_t)(kk + 1) * (2 * I_)];
        pb[j].z = colp[(size_t)(kk + 2) * (2 * I_)];
        pb[j].w = colp[(size_t)(kk + 3) * (2 * I_)];
    }
#pragma unroll
    for (int j = 0; j < 4; j++) { sts4_tf32(aaddr[j], pa[j]); sts4_tf32(baddr[j], pb[j]); }
    __syncthreads();

    for (int it = 0; it < NITER; ++it) {
        int nxt = it + 1;
        if (nxt < NITER) {
            int k0 = nxt * BK;
#pragma unroll
            for (int j = 0; j < 4; j++) {
                pa[j] = arow[j] ? *(const float4*)(arow[j] + k0 + aq * 4) : make_float4(0, 0, 0, 0);
                int kk = k0 + (2 * j + bqh) * 4;
                pb[j].x = colp[(size_t)(kk + 0) * (2 * I_)];
                pb[j].y = colp[(size_t)(kk + 1) * (2 * I_)];
                pb[j].z = colp[(size_t)(kk + 2) * (2 * I_)];
                pb[j].w = colp[(size_t)(kk + 3) * (2 * I_)];
            }
        }
        uint32_t Ast = Abase + (it & 1) * STAGE_BYTES;
        uint32_t Bst = Bbase + (it & 1) * STAGE_BYTES;
#pragma unroll
        for (int k8 = 0; k8 < 4; k8++) {
            int kk = k8 * 8;
            uint32_t af[2][4], bf[8][2];
#pragma unroll
            for (int mt = 0; mt < 2; mt++) {
                int r0 = wm + mt * 16 + gid;
                af[mt][0] = lds32(Ast + (r0 * SA + kk + tig) * 4);
                af[mt][1] = lds32(Ast + ((r0 + 8) * SA + kk + tig) * 4);
                af[mt][2] = lds32(Ast + (r0 * SA + kk + tig + 4) * 4);
                af[mt][3] = lds32(Ast + ((r0 + 8) * SA + kk + tig + 4) * 4);
            }
#pragma unroll
            for (int nt = 0; nt < 8; nt++) {
                int c = wn + nt * 8 + gid;
                bf[nt][0] = lds32(Bst + (c * SA + kk + tig) * 4);
                bf[nt][1] = lds32(Bst + (c * SA + kk + tig + 4) * 4);
            }
#pragma unroll
            for (int mt = 0; mt < 2; mt++)
#pragma unroll
                for (int nt = 0; nt < 8; nt++)
                    mma_tf32(acc[mt][nt], af[mt], bf[nt]);
        }
        if (nxt < NITER) {
            uint32_t so = (nxt & 1) * STAGE_BYTES;
#pragma unroll
            for (int j = 0; j < 4; j++) { sts4_tf32(aaddr[j] + so, pa[j]); sts4_tf32(baddr[j] + so, pb[j]); }
            __syncthreads();
        }
    }

    // epilogue: c0=gate, c1=up at same logical col; rows gid, gid+8
    int off = g_actoff[e];
#pragma unroll
    for (int mt = 0; mt < 2; mt++) {
        int i0 = rowBase + wm + mt * 16 + gid;
        int i1 = i0 + 8;
        float* o0 = g_act + (size_t)(off + i0) * I_;
        float* o1 = g_act + (size_t)(off + i1) * I_;
#pragma unroll
        for (int nt = 0; nt < 8; nt++) {
            int gcol = nbase + (wn >> 1) + nt * 4 + tig;
            if (i0 < cnt) o0[gcol] = silu_f(acc[mt][nt][0]) * acc[mt][nt][1];
            if (i1 < cnt) o1[gcol] = silu_f(acc[mt][nt][2]) * acc[mt][nt][3];
        }
    }
}

// =================== GEMM2: out2 = w * (act @ W2) ===================
__global__ __launch_bounds__(256, 1)
void gemm2_kernel(const float* __restrict__ W2) {
    int e = blockIdx.z;
    int cnt = g_counts[e];
    int rowBase = blockIdx.y * BM;
    if (rowBase >= cnt) return;
    int nbase = blockIdx.x * BN;
    int off = g_actoff[e];

    extern __shared__ float smem[];
    uint32_t sb = smem_u32(smem);
    uint32_t Abase = sb + 512;
    uint32_t Bbase = Abase + 18432;

    int tid = threadIdx.x;
    int wid = tid >> 5, lane = tid & 31;
    int gid = lane >> 2, tig = lane & 3;
    int wm = (wid & 3) * 32, wn = (wid >> 2) * 64;

    const int aq = tid & 7;
    const int am0 = tid >> 3;
    const int bs = tid & 127;
    const int bqh = tid >> 7;
    const float* arow[4];
#pragma unroll
    for (int j = 0; j < 4; j++) {
        int i = rowBase + am0 + j * 32;
        arow[j] = (i < cnt) ? (g_act + (size_t)(off + i) * I_) : nullptr;
    }
    const float* colp = W2 + (size_t)e * I_ * H_ + nbase + bs;
    uint32_t aaddr[4], baddr[4];
#pragma unroll
    for (int j = 0; j < 4; j++) {
        aaddr[j] = Abase + (am0 + j * 32) * (SA * 4) + aq * 16;
        baddr[j] = Bbase + bs * (SA * 4) + (2 * j + bqh) * 16;
    }

    float acc[2][8][4];
#pragma unroll
    for (int mt = 0; mt < 2; mt++)
#pragma unroll
        for (int nt = 0; nt < 8; nt++)
#pragma unroll
            for (int r = 0; r < 4; r++) acc[mt][nt][r] = 0.0f;

    float4 pa[4], pb[4];
    const int NITER = I_ / BK;   // 128

#pragma unroll
    for (int j = 0; j < 4; j++) {
        pa[j] = arow[j] ? *(const float4*)(arow[j] + aq * 4) : make_float4(0, 0, 0, 0);
        int kk = (2 * j + bqh) * 4;
        pb[j].x = colp[(size_t)(kk + 0) * H_];
        pb[j].y = colp[(size_t)(kk + 1) * H_];
        pb[j].z = colp[(size_t)(kk + 2) * H_];
        pb[j].w = colp[(size_t)(kk + 3) * H_];
    }
#pragma unroll
    for (int j = 0; j < 4; j++) { sts4_tf32(aaddr[j], pa[j]); sts4_tf32(baddr[j], pb[j]); }
    __syncthreads();

    for (int it = 0; it < NITER; ++it) {
        int nxt = it + 1;
        if (nxt < NITER) {
            int k0 = nxt * BK;
#pragma unroll
            for (int j = 0; j < 4; j++) {
                pa[j] = arow[j] ? *(const float4*)(arow[j] + k0 + aq * 4) : make_float4(0, 0, 0, 0);
                int kk = k0 + (2 * j + bqh) * 4;
                pb[j].x = colp[(size_t)(kk + 0) * H_];
                pb[j].y = colp[(size_t)(kk + 1) * H_];
                pb[j].z = colp[(size_t)(kk + 2) * H_];
                pb[j].w = colp[(size_t)(kk + 3) * H_];
            }
        }
        uint32_t Ast = Abase + (it & 1) * STAGE_BYTES;
        uint32_t Bst = Bbase + (it & 1) * STAGE_BYTES;
#pragma unroll
        for (int k8 = 0; k8 < 4; k8++) {
            int kk = k8 * 8;
            uint32_t af[2][4], bf[8][2];
#pragma unroll
            for (int mt = 0; mt < 2; mt++) {
                int r0 = wm + mt * 16 + gid;
                af[mt][0] = lds32(Ast + (r0 * SA + kk + tig) * 4);
                af[mt][1] = lds32(Ast + ((r0 + 8) * SA + kk + tig) * 4);
                af[mt][2] = lds32(Ast + (r0 * SA + kk + tig + 4) * 4);
                af[mt][3] = lds32(Ast + ((r0 + 8) * SA + kk + tig + 4) * 4);
            }
#pragma unroll
            for (int nt = 0; nt < 8; nt++) {
                int c = wn + nt * 8 + gid;
                bf[nt][0] = lds32(Bst + (c * SA + kk + tig) * 4);
                bf[nt][1] = lds32(Bst + (c * SA + kk + tig + 4) * 4);
            }
#pragma unroll
            for (int mt = 0; mt < 2; mt++)
#pragma unroll
                for (int nt = 0; nt < 8; nt++)
                    mma_tf32(acc[mt][nt], af[mt], bf[nt]);
        }
        if (nxt < NITER) {
            uint32_t so = (nxt & 1) * STAGE_BYTES;
#pragma unroll
            for (int j = 0; j < 4; j++) { sts4_tf32(aaddr[j] + so, pa[j]); sts4_tf32(baddr[j] + so, pb[j]); }
            __syncthreads();
        }
    }

#pragma unroll
    for (int mt = 0; mt < 2; mt++) {
        int i0 = rowBase + wm + mt * 16 + gid;
        int i1 = i0 + 8;
        float w0 = (i0 < cnt) ? g_w[e * T_ + i0] : 0.0f;
        float w1 = (i1 < cnt) ? g_w[e * T_ + i1] : 0.0f;
        float* o0 = g_out2 + (size_t)(off + i0) * H_;
        float* o1 = g_out2 + (size_t)(off + i1) * H_;
#pragma unroll
        for (int nt = 0; nt < 8; nt++) {
            int n = nbase + wn + nt * 8 + tig * 2;
            if (i0 < cnt) {
                float2 v = make_float2(w0 * acc[mt][nt][0], w0 * acc[mt][nt][1]);
                *(float2*)(o0 + n) = v;
            }
            if (i1 < cnt) {
                float2 v = make_float2(w1 * acc[mt][nt][2], w1 * acc[mt][nt][3]);
                *(float2*)(o1 + n) = v;
            }
        }
    }
}

// =================== combine ===================
__global__ void combine_kernel(float* __restrict__ out) {
    int t = blockIdx.x;
    __shared__ int rows[KMAX];
    int k = g_k;
    if (threadIdx.x < k) {
        int ep = g_slot_row[t * KMAX + threadIdx.x];
        int e = ep / T_;
        int p = ep - e * T_;
        rows[threadIdx.x] = g_actoff[e] + p;
    }
    __syncthreads();
    for (int h4 = threadIdx.x; h4 < H_ / 4; h4 += blockDim.x) {
        float4 s = make_float4(0.f, 0.f, 0.f, 0.f);
        for (int j = 0; j < k; j++) {
            float4 v = *(const float4*)(g_out2 + (size_t)rows[j] * H_ + h4 * 4);
            s.x += v.x; s.y += v.y; s.z += v.z; s.w += v.w;
        }
        *(float4*)(out + (size_t)t * H_ + h4 * 4) = s;
    }
}

// =================== launch ===================
extern "C" void kernel_launch(void* const* d_in, const int* in_sizes, int n_in,
                              void* d_out, int out_size) {
    const float* X   = (const float*)d_in[0];
    const float* RL  = (const float*)d_in[1];
    const float* W13 = (const float*)d_in[2];
    const float* W2  = (const float*)d_in[3];
    const int*   tk  = (n_in > 4) ? (const int*)d_in[4] : nullptr;

    cudaFuncSetAttribute(gemm1_kernel, cudaFuncAttributeMaxDynamicSharedMemorySize, SMEM_BYTES);
    cudaFuncSetAttribute(gemm2_kernel, cudaFuncAttributeMaxDynamicSharedMemorySize, SMEM_BYTES);

    init_kernel<<<1, 32>>>(tk);
    route_kernel<<<(T_ + 127) / 128, 128>>>(RL);
    scan_kernel<<<1, 1>>>();
    gemm1_kernel<<<dim3(I_ / 64, ROWCAP / BM, E_), 256, SMEM_BYTES>>>(X, W13);
    gemm2_kernel<<<dim3(H_ / BN, ROWCAP / BM, E_), 256, SMEM_BYTES>>>(W2);
    combine_kernel<<<T_, 256>>>((float*)d_out);
}

// round 5
// speedup vs baseline: 3.2843x; 1.2005x over previous
#include <cuda_runtime.h>
#include <cstdint>

#define T_ 4096
#define E_ 8
#define H_ 2048
#define I_ 4096
#define KMAX 2
#define ROWCAP (T_ * KMAX)

#define BM 128
#define BN 256            // physical cols per block
#define BK 32
#define SA 36             // padded row stride (floats)
#define A_BYTES (BM * SA * 4)            // 18432
#define B_BYTES (BN * SA * 4)            // 36864
#define STAGE_BYTES (A_BYTES + B_BYTES)  // 55296
#define SMEM_BYTES (512 + 2 * STAGE_BYTES)

// ---------------- scratch ----------------
__device__ int   g_k;
__device__ int   g_counts[E_];
__device__ int   g_actoff[E_];
__device__ int   g_tok[E_ * T_];
__device__ float g_w[E_ * T_];
__device__ int   g_slot_row[T_ * KMAX];
__device__ float g_act[(size_t)ROWCAP * I_];
__device__ float g_out2[(size_t)ROWCAP * H_];

__device__ __forceinline__ float silu_f(float x) { return x / (1.0f + __expf(-x)); }

__device__ __forceinline__ uint32_t smem_u32(const void* p) {
    return (uint32_t)__cvta_generic_to_shared(p);
}
__device__ __forceinline__ void sts4_tf32(uint32_t addr, float4 v) {
    uint32_t a, b, c, d;
    asm volatile("cvt.rna.tf32.f32 %0, %1;" : "=r"(a) : "f"(v.x));
    asm volatile("cvt.rna.tf32.f32 %0, %1;" : "=r"(b) : "f"(v.y));
    asm volatile("cvt.rna.tf32.f32 %0, %1;" : "=r"(c) : "f"(v.z));
    asm volatile("cvt.rna.tf32.f32 %0, %1;" : "=r"(d) : "f"(v.w));
    asm volatile("st.shared.v4.b32 [%0], {%1,%2,%3,%4};"
                 :: "r"(addr), "r"(a), "r"(b), "r"(c), "r"(d));
}
__device__ __forceinline__ uint32_t lds32(uint32_t addr) {
    uint32_t v;
    asm volatile("ld.shared.b32 %0, [%1];" : "=r"(v) : "r"(addr));
    return v;
}
__device__ __forceinline__ void mma_tf32(float* c, const uint32_t* a, const uint32_t* b) {
    asm volatile(
        "mma.sync.aligned.m16n8k8.row.col.f32.tf32.tf32.f32 "
        "{%0,%1,%2,%3}, {%4,%5,%6,%7}, {%8,%9}, {%0,%1,%2,%3};"
        : "+f"(c[0]), "+f"(c[1]), "+f"(c[2]), "+f"(c[3])
        : "r"(a[0]), "r"(a[1]), "r"(a[2]), "r"(a[3]), "r"(b[0]), "r"(b[1]));
}

// =================== init / route / scan ===================
__global__ void init_kernel(const int* topk_ptr) {
    if (threadIdx.x == 0) {
        int k = topk_ptr ? *topk_ptr : 2;
        if (k < 1) k = 1;
        if (k > KMAX) k = KMAX;
        g_k = k;
    }
    if (threadIdx.x < E_) g_counts[threadIdx.x] = 0;
}

__global__ void route_kernel(const float* __restrict__ logits) {
    int t = blockIdx.x * blockDim.x + threadIdx.x;
    if (t >= T_) return;
    int k = g_k;
    float l[E_];
    float mx = -1e30f;
#pragma unroll
    for (int e = 0; e < E_; e++) { l[e] = logits[t * E_ + e]; mx = fmaxf(mx, l[e]); }
    bool used[E_];
#pragma unroll
    for (int e = 0; e < E_; e++) used[e] = false;
    int sel[KMAX]; float sw[KMAX]; float wsum = 0.0f;
    for (int j = 0; j < k; j++) {
        int best = 0; float bv = -1e30f;
#pragma unroll
        for (int e = 0; e < E_; e++)
            if (!used[e] && l[e] > bv) { bv = l[e]; best = e; }
        used[best] = true; sel[j] = best;
        float w = __expf(l[best] - mx);
        sw[j] = w; wsum += w;
    }
    for (int j = 0; j < k; j++) {
        int e = sel[j];
        float w = sw[j] / wsum;
        int p = atomicAdd(&g_counts[e], 1);
        g_tok[e * T_ + p] = t;
        g_w[e * T_ + p] = w;
        g_slot_row[t * KMAX + j] = e * T_ + p;
    }
}

__global__ void scan_kernel() {
    int off = 0;
    for (int e = 0; e < E_; e++) { g_actoff[e] = off; off += g_counts[e]; }
}

// =================== GEMM1 ===================
// block: 128 gathered rows x 128 logical cols (256 phys: even=gate, odd=up)
// 8 warps as 2(M) x 4(N), warp tile 64x64 phys -> mt=4, nt=8
__global__ __launch_bounds__(256, 1)
void gemm1_kernel(const float* __restrict__ X, const float* __restrict__ W13) {
    int e = blockIdx.z;
    int cnt = g_counts[e];
    int rowBase = blockIdx.y * BM;
    if (rowBase >= cnt) return;
    int nbaseL = blockIdx.x * 128;   // logical col base

    extern __shared__ float smem[];
    int* toks = (int*)smem;
    uint32_t sb = smem_u32(smem);
    uint32_t Abase = sb + 512;
    uint32_t Bbase = Abase + A_BYTES;

    int tid = threadIdx.x;
    int wid = tid >> 5, lane = tid & 31;
    int gid = lane >> 2, tig = lane & 3;
    int wm = (wid & 1) * 64, wn = (wid >> 1) * 64;

    if (tid < BM) {
        int i = rowBase + tid;
        toks[tid] = (i < cnt) ? g_tok[e * T_ + i] : -1;
    }
    __syncthreads();

    // A loader: aq = tid&7 (16B unit), rows am0 + j*32
    const int aq = tid & 7;
    const int am0 = tid >> 3;
    const float* arow[4];
#pragma unroll
    for (int j = 0; j < 4; j++) {
        int tok = toks[am0 + j * 32];
        arow[j] = (tok >= 0) ? (X + (size_t)tok * H_) : nullptr;
    }
    // B loader: one phys col per thread (s = tid): even=gate, odd=up
    const int s = tid;
    const float* colp = W13 + (size_t)e * H_ * (2 * I_) + nbaseL + (s >> 1) + ((s & 1) ? I_ : 0);
    uint32_t aaddr[4], baddr;
#pragma unroll
    for (int j = 0; j < 4; j++) aaddr[j] = Abase + (am0 + j * 32) * (SA * 4) + aq * 16;
    baddr = Bbase + s * (SA * 4);

    float acc[4][8][4];
#pragma unroll
    for (int mt = 0; mt < 4; mt++)
#pragma unroll
        for (int nt = 0; nt < 8; nt++)
#pragma unroll
            for (int r = 0; r < 4; r++) acc[mt][nt][r] = 0.0f;

    float4 pa[4], pb[8];
    const int NITER = H_ / BK;   // 64

    // prologue
#pragma unroll
    for (int j = 0; j < 4; j++)
        pa[j] = arow[j] ? *(const float4*)(arow[j] + aq * 4) : make_float4(0, 0, 0, 0);
#pragma unroll
    for (int j = 0; j < 8; j++) {
        int kk = j * 4;
        pb[j].x = colp[(size_t)(kk + 0) * (2 * I_)];
        pb[j].y = colp[(size_t)(kk + 1) * (2 * I_)];
        pb[j].z = colp[(size_t)(kk + 2) * (2 * I_)];
        pb[j].w = colp[(size_t)(kk + 3) * (2 * I_)];
    }
#pragma unroll
    for (int j = 0; j < 4; j++) sts4_tf32(aaddr[j], pa[j]);
#pragma unroll
    for (int j = 0; j < 8; j++) sts4_tf32(baddr + j * 16, pb[j]);
    __syncthreads();

    for (int it = 0; it < NITER; ++it) {
        int nxt = it + 1;
        if (nxt < NITER) {
            int k0 = nxt * BK;
#pragma unroll
            for (int j = 0; j < 4; j++)
                pa[j] = arow[j] ? *(const float4*)(arow[j] + k0 + aq * 4) : make_float4(0, 0, 0, 0);
#pragma unroll
            for (int j = 0; j < 8; j++) {
                int kk = k0 + j * 4;
                pb[j].x = colp[(size_t)(kk + 0) * (2 * I_)];
                pb[j].y = colp[(size_t)(kk + 1) * (2 * I_)];
                pb[j].z = colp[(size_t)(kk + 2) * (2 * I_)];
                pb[j].w = colp[(size_t)(kk + 3) * (2 * I_)];
            }
        }
        uint32_t Ast = Abase + (it & 1) * STAGE_BYTES;
        uint32_t Bst = Bbase + (it & 1) * STAGE_BYTES;
#pragma unroll
        for (int k8 = 0; k8 < 4; k8++) {
            int kk = k8 * 8;
            uint32_t af[4][4], bf[8][2];
#pragma unroll
            for (int mt = 0; mt < 4; mt++) {
                int r0 = wm + mt * 16 + gid;
                af[mt][0] = lds32(Ast + (r0 * SA + kk + tig) * 4);
                af[mt][1] = lds32(Ast + ((r0 + 8) * SA + kk + tig) * 4);
                af[mt][2] = lds32(Ast + (r0 * SA + kk + tig + 4) * 4);
                af[mt][3] = lds32(Ast + ((r0 + 8) * SA + kk + tig + 4) * 4);
            }
#pragma unroll
            for (int nt = 0; nt < 8; nt++) {
                int c = wn + nt * 8 + gid;
                bf[nt][0] = lds32(Bst + (c * SA + kk + tig) * 4);
                bf[nt][1] = lds32(Bst + (c * SA + kk + tig + 4) * 4);
            }
#pragma unroll
            for (int mt = 0; mt < 4; mt++)
#pragma unroll
                for (int nt = 0; nt < 8; nt++)
                    mma_tf32(acc[mt][nt], af[mt], bf[nt]);
        }
        if (nxt < NITER) {
            uint32_t so = (nxt & 1) * STAGE_BYTES;
#pragma unroll
            for (int j = 0; j < 4; j++) sts4_tf32(aaddr[j] + so, pa[j]);
#pragma unroll
            for (int j = 0; j < 8; j++) sts4_tf32(baddr + so + j * 16, pb[j]);
            __syncthreads();
        }
    }

    // epilogue: (c0,c1) = (gate, up) at same logical col
    int off = g_actoff[e];
#pragma unroll
    for (int mt = 0; mt < 4; mt++) {
        int i0 = rowBase + wm + mt * 16 + gid;
        int i1 = i0 + 8;
        float* o0 = g_act + (size_t)(off + i0) * I_;
        float* o1 = g_act + (size_t)(off + i1) * I_;
#pragma unroll
        for (int nt = 0; nt < 8; nt++) {
            int gcol = nbaseL + (wn >> 1) + nt * 4 + tig;
            if (i0 < cnt) o0[gcol] = silu_f(acc[mt][nt][0]) * acc[mt][nt][1];
            if (i1 < cnt) o1[gcol] = silu_f(acc[mt][nt][2]) * acc[mt][nt][3];
        }
    }
}

// =================== GEMM2 ===================
// block: 128 rows x 256 cols, same warp geometry
__global__ __launch_bounds__(256, 1)
void gemm2_kernel(const float* __restrict__ W2) {
    int e = blockIdx.z;
    int cnt = g_counts[e];
    int rowBase = blockIdx.y * BM;
    if (rowBase >= cnt) return;
    int nbase = blockIdx.x * BN;
    int off = g_actoff[e];

    extern __shared__ float smem[];
    uint32_t sb = smem_u32(smem);
    uint32_t Abase = sb + 512;
    uint32_t Bbase = Abase + A_BYTES;

    int tid = threadIdx.x;
    int wid = tid >> 5, lane = tid & 31;
    int gid = lane >> 2, tig = lane & 3;
    int wm = (wid & 1) * 64, wn = (wid >> 1) * 64;

    const int aq = tid & 7;
    const int am0 = tid >> 3;
    const float* arow[4];
#pragma unroll
    for (int j = 0; j < 4; j++) {
        int i = rowBase + am0 + j * 32;
        arow[j] = (i < cnt) ? (g_act + (size_t)(off + i) * I_) : nullptr;
    }
    const int s = tid;
    const float* colp = W2 + (size_t)e * I_ * H_ + nbase + s;
    uint32_t aaddr[4], baddr;
#pragma unroll
    for (int j = 0; j < 4; j++) aaddr[j] = Abase + (am0 + j * 32) * (SA * 4) + aq * 16;
    baddr = Bbase + s * (SA * 4);

    float acc[4][8][4];
#pragma unroll
    for (int mt = 0; mt < 4; mt++)
#pragma unroll
        for (int nt = 0; nt < 8; nt++)
#pragma unroll
            for (int r = 0; r < 4; r++) acc[mt][nt][r] = 0.0f;

    float4 pa[4], pb[8];
    const int NITER = I_ / BK;   // 128

#pragma unroll
    for (int j = 0; j < 4; j++)
        pa[j] = arow[j] ? *(const float4*)(arow[j] + aq * 4) : make_float4(0, 0, 0, 0);
#pragma unroll
    for (int j = 0; j < 8; j++) {
        int kk = j * 4;
        pb[j].x = colp[(size_t)(kk + 0) * H_];
        pb[j].y = colp[(size_t)(kk + 1) * H_];
        pb[j].z = colp[(size_t)(kk + 2) * H_];
        pb[j].w = colp[(size_t)(kk + 3) * H_];
    }
#pragma unroll
    for (int j = 0; j < 4; j++) sts4_tf32(aaddr[j], pa[j]);
#pragma unroll
    for (int j = 0; j < 8; j++) sts4_tf32(baddr + j * 16, pb[j]);
    __syncthreads();

    for (int it = 0; it < NITER; ++it) {
        int nxt = it + 1;
        if (nxt < NITER) {
            int k0 = nxt * BK;
#pragma unroll
            for (int j = 0; j < 4; j++)
                pa[j] = arow[j] ? *(const float4*)(arow[j] + k0 + aq * 4) : make_float4(0, 0, 0, 0);
#pragma unroll
            for (int j = 0; j < 8; j++) {
                int kk = k0 + j * 4;
                pb[j].x = colp[(size_t)(kk + 0) * H_];
                pb[j].y = colp[(size_t)(kk + 1) * H_];
                pb[j].z = colp[(size_t)(kk + 2) * H_];
                pb[j].w = colp[(size_t)(kk + 3) * H_];
            }
        }
        uint32_t Ast = Abase + (it & 1) * STAGE_BYTES;
        uint32_t Bst = Bbase + (it & 1) * STAGE_BYTES;
#pragma unroll
        for (int k8 = 0; k8 < 4; k8++) {
            int kk = k8 * 8;
            uint32_t af[4][4], bf[8][2];
#pragma unroll
            for (int mt = 0; mt < 4; mt++) {
                int r0 = wm + mt * 16 + gid;
                af[mt][0] = lds32(Ast + (r0 * SA + kk + tig) * 4);
                af[mt][1] = lds32(Ast + ((r0 + 8) * SA + kk + tig) * 4);
                af[mt][2] = lds32(Ast + (r0 * SA + kk + tig + 4) * 4);
                af[mt][3] = lds32(Ast + ((r0 + 8) * SA + kk + tig + 4) * 4);
            }
#pragma unroll
            for (int nt = 0; nt < 8; nt++) {
                int c = wn + nt * 8 + gid;
                bf[nt][0] = lds32(Bst + (c * SA + kk + tig) * 4);
                bf[nt][1] = lds32(Bst + (c * SA + kk + tig + 4) * 4);
            }
#pragma unroll
            for (int mt = 0; mt < 4; mt++)
#pragma unroll
                for (int nt = 0; nt < 8; nt++)
                    mma_tf32(acc[mt][nt], af[mt], bf[nt]);
        }
        if (nxt < NITER) {
            uint32_t so = (nxt & 1) * STAGE_BYTES;
#pragma unroll
            for (int j = 0; j < 4; j++) sts4_tf32(aaddr[j] + so, pa[j]);
#pragma unroll
            for (int j = 0; j < 8; j++) sts4_tf32(baddr + so + j * 16, pb[j]);
            __syncthreads();
        }
    }

#pragma unroll
    for (int mt = 0; mt < 4; mt++) {
        int i0 = rowBase + wm + mt * 16 + gid;
        int i1 = i0 + 8;
        float w0 = (i0 < cnt) ? g_w[e * T_ + i0] : 0.0f;
        float w1 = (i1 < cnt) ? g_w[e * T_ + i1] : 0.0f;
        float* o0 = g_out2 + (size_t)(off + i0) * H_;
        float* o1 = g_out2 + (size_t)(off + i1) * H_;
#pragma unroll
        for (int nt = 0; nt < 8; nt++) {
            int n = nbase + wn + nt * 8 + tig * 2;
            if (i0 < cnt) *(float2*)(o0 + n) = make_float2(w0 * acc[mt][nt][0], w0 * acc[mt][nt][1]);
            if (i1 < cnt) *(float2*)(o1 + n) = make_float2(w1 * acc[mt][nt][2], w1 * acc[mt][nt][3]);
        }
    }
}

// =================== combine ===================
__global__ void combine_kernel(float* __restrict__ out) {
    int t = blockIdx.x;
    __shared__ int rows[KMAX];
    int k = g_k;
    if (threadIdx.x < k) {
        int ep = g_slot_row[t * KMAX + threadIdx.x];
        int e = ep / T_;
        int p = ep - e * T_;
        rows[threadIdx.x] = g_actoff[e] + p;
    }
    __syncthreads();
    for (int h4 = threadIdx.x; h4 < H_ / 4; h4 += blockDim.x) {
        float4 s = make_float4(0.f, 0.f, 0.f, 0.f);
        for (int j = 0; j < k; j++) {
            float4 v = *(const float4*)(g_out2 + (size_t)rows[j] * H_ + h4 * 4);
            s.x += v.x; s.y += v.y; s.z += v.z; s.w += v.w;
        }
        *(float4*)(out + (size_t)t * H_ + h4 * 4) = s;
    }
}

// =================== launch ===================
extern "C" void kernel_launch(void* const* d_in, const int* in_sizes, int n_in,
                              void* d_out, int out_size) {
    const float* X   = (const float*)d_in[0];
    const float* RL  = (const float*)d_in[1];
    const float* W13 = (const float*)d_in[2];
    const float* W2  = (const float*)d_in[3];
    const int*   tk  = (n_in > 4) ? (const int*)d_in[4] : nullptr;

    cudaFuncSetAttribute(gemm1_kernel, cudaFuncAttributeMaxDynamicSharedMemorySize, SMEM_BYTES);
    cudaFuncSetAttribute(gemm2_kernel, cudaFuncAttributeMaxDynamicSharedMemorySize, SMEM_BYTES);

    init_kernel<<<1, 32>>>(tk);
    route_kernel<<<(T_ + 127) / 128, 128>>>(RL);
    scan_kernel<<<1, 1>>>();
    gemm1_kernel<<<dim3(I_ / 128, ROWCAP / BM, E_), 256, SMEM_BYTES>>>(X, W13);
    gemm2_kernel<<<dim3(H_ / BN, ROWCAP / BM, E_), 256, SMEM_BYTES>>>(W2);
    combine_kernel<<<T_, 256>>>((float*)d_out);
}